// round 1
// baseline (speedup 1.0000x reference)
#include <cuda_runtime.h>

// Shapes (fixed by the problem): B=4, T=2048, C=768, H=12, D=64
#define B_    4
#define T_    2048
#define C_    768
#define H_    12
#define D_    64
#define BH_   (B_ * H_)        // 48
#define M_    (B_ * T_)        // 8192
#define N3_   (3 * C_)         // 2304

// Scratch (device globals — no allocation in kernel_launch)
__device__ float g_q[BH_ * T_ * D_];   // [b,h,t,d]
__device__ float g_k[BH_ * T_ * D_];
__device__ float g_v[BH_ * T_ * D_];
__device__ float g_y[M_ * C_];         // [b*t, c] attention output

// ---------------------------------------------------------------------------
// GEMM 1: qkv = x @ w_attn + b_attn, scattered into g_q/g_k/g_v [b,h,t,d]
// 64x64 tile, BK=16, 256 threads, 4x4 per thread.
// ---------------------------------------------------------------------------
__global__ __launch_bounds__(256) void gemm_qkv_kernel(
    const float* __restrict__ X,     // [8192, 768]
    const float* __restrict__ W,     // [768, 2304]
    const float* __restrict__ bias)  // [2304]
{
    __shared__ float As[16][68];  // [k][m]
    __shared__ float Bs[16][68];  // [k][n]

    const int m0 = blockIdx.y * 64;
    const int n0 = blockIdx.x * 64;
    const int tid = threadIdx.x;
    const int tx = tid & 15, ty = tid >> 4;
    const int tx4 = tx << 2, ty4 = ty << 2;

    const int a_row = tid >> 2;          // 0..63
    const int a_kc  = (tid & 3) << 2;    // 0,4,8,12
    const int b_row = tid >> 4;          // 0..15
    const int b_col = (tid & 15) << 2;   // 0..60

    float acc[4][4];
    #pragma unroll
    for (int i = 0; i < 4; ++i)
        #pragma unroll
        for (int j = 0; j < 4; ++j) acc[i][j] = 0.0f;

    const float* Aptr = X + (m0 + a_row) * C_ + a_kc;
    const float* Bptr = W + b_row * N3_ + n0 + b_col;

    for (int k0 = 0; k0 < C_; k0 += 16) {
        float4 av = *(const float4*)(Aptr + k0);
        float4 bv = *(const float4*)(Bptr + k0 * N3_);
        __syncthreads();
        As[a_kc + 0][a_row] = av.x;
        As[a_kc + 1][a_row] = av.y;
        As[a_kc + 2][a_row] = av.z;
        As[a_kc + 3][a_row] = av.w;
        *(float4*)&Bs[b_row][b_col] = bv;
        __syncthreads();
        #pragma unroll
        for (int kk = 0; kk < 16; ++kk) {
            float4 a = *(const float4*)&As[kk][ty4];
            float4 b = *(const float4*)&Bs[kk][tx4];
            acc[0][0] += a.x * b.x; acc[0][1] += a.x * b.y; acc[0][2] += a.x * b.z; acc[0][3] += a.x * b.w;
            acc[1][0] += a.y * b.x; acc[1][1] += a.y * b.y; acc[1][2] += a.y * b.z; acc[1][3] += a.y * b.w;
            acc[2][0] += a.z * b.x; acc[2][1] += a.z * b.y; acc[2][2] += a.z * b.z; acc[2][3] += a.z * b.w;
            acc[3][0] += a.w * b.x; acc[3][1] += a.w * b.y; acc[3][2] += a.w * b.z; acc[3][3] += a.w * b.w;
        }
    }

    // Epilogue: n-tile lies entirely within one of {q,k,v} and one head (64 | 768)
    const int which = n0 / C_;              // 0=q,1=k,2=v
    const int hh    = (n0 % C_) >> 6;       // head
    const int b     = m0 >> 11;             // batch (2048 rows per batch, 64 | 2048)
    const int t0    = m0 & (T_ - 1);
    float* dst = (which == 0) ? g_q : ((which == 1) ? g_k : g_v);
    const int base = ((b * H_ + hh) * T_ + t0) * D_;

    float4 bv4 = *(const float4*)&bias[n0 + tx4];
    #pragma unroll
    for (int i = 0; i < 4; ++i) {
        float4 o;
        o.x = acc[i][0] + bv4.x;
        o.y = acc[i][1] + bv4.y;
        o.z = acc[i][2] + bv4.z;
        o.w = acc[i][3] + bv4.w;
        *(float4*)&dst[base + (ty4 + i) * D_ + tx4] = o;
    }
}

// ---------------------------------------------------------------------------
// GEMM 2: out = g_y @ w_proj + b_proj
// ---------------------------------------------------------------------------
__global__ __launch_bounds__(256) void gemm_proj_kernel(
    const float* __restrict__ W,     // [768, 768]
    const float* __restrict__ bias,  // [768]
    float* __restrict__ out)         // [8192, 768]
{
    __shared__ float As[16][68];
    __shared__ float Bs[16][68];

    const int m0 = blockIdx.y * 64;
    const int n0 = blockIdx.x * 64;
    const int tid = threadIdx.x;
    const int tx = tid & 15, ty = tid >> 4;
    const int tx4 = tx << 2, ty4 = ty << 2;

    const int a_row = tid >> 2;
    const int a_kc  = (tid & 3) << 2;
    const int b_row = tid >> 4;
    const int b_col = (tid & 15) << 2;

    float acc[4][4];
    #pragma unroll
    for (int i = 0; i < 4; ++i)
        #pragma unroll
        for (int j = 0; j < 4; ++j) acc[i][j] = 0.0f;

    const float* Aptr = g_y + (m0 + a_row) * C_ + a_kc;
    const float* Bptr = W + b_row * C_ + n0 + b_col;

    for (int k0 = 0; k0 < C_; k0 += 16) {
        float4 av = *(const float4*)(Aptr + k0);
        float4 bv = *(const float4*)(Bptr + k0 * C_);
        __syncthreads();
        As[a_kc + 0][a_row] = av.x;
        As[a_kc + 1][a_row] = av.y;
        As[a_kc + 2][a_row] = av.z;
        As[a_kc + 3][a_row] = av.w;
        *(float4*)&Bs[b_row][b_col] = bv;
        __syncthreads();
        #pragma unroll
        for (int kk = 0; kk < 16; ++kk) {
            float4 a = *(const float4*)&As[kk][ty4];
            float4 b = *(const float4*)&Bs[kk][tx4];
            acc[0][0] += a.x * b.x; acc[0][1] += a.x * b.y; acc[0][2] += a.x * b.z; acc[0][3] += a.x * b.w;
            acc[1][0] += a.y * b.x; acc[1][1] += a.y * b.y; acc[1][2] += a.y * b.z; acc[1][3] += a.y * b.w;
            acc[2][0] += a.z * b.x; acc[2][1] += a.z * b.y; acc[2][2] += a.z * b.z; acc[2][3] += a.z * b.w;
            acc[3][0] += a.w * b.x; acc[3][1] += a.w * b.y; acc[3][2] += a.w * b.z; acc[3][3] += a.w * b.w;
        }
    }

    float4 bv4 = *(const float4*)&bias[n0 + tx4];
    #pragma unroll
    for (int i = 0; i < 4; ++i) {
        float4 o;
        o.x = acc[i][0] + bv4.x;
        o.y = acc[i][1] + bv4.y;
        o.z = acc[i][2] + bv4.z;
        o.w = acc[i][3] + bv4.w;
        *(float4*)&out[(m0 + ty4 + i) * C_ + n0 + tx4] = o;
    }
}

// ---------------------------------------------------------------------------
// Flash attention (fp32, online softmax). One block = 64 queries of one (b,h).
// 256 threads as 16x16; each thread owns a 4(row)x4(col) microtile.
// Shared: sQ [d][r] (scaled), sK [d][c] (reused as P [k][r]), sV [k][c].
// ---------------------------------------------------------------------------
#define APITCH 68
#define ATT_SMEM (3 * 64 * APITCH * 4)

__global__ __launch_bounds__(256) void attn_kernel()
{
    extern __shared__ float smem[];
    float* sQ = smem;                  // [64][68] as [d][r]
    float* sK = smem + 64 * APITCH;    // [64][68] as [d][c]; reused as P [k][r]
    float* sV = smem + 2 * 64 * APITCH;// [64][68] as [k][c]

    const int qt = blockIdx.x;         // 0..31
    const int bh = blockIdx.y;         // 0..47
    const int b  = bh / H_;
    const int h  = bh % H_;
    const int q0 = qt * 64;

    const int tid = threadIdx.x;
    const int tx = tid & 15, ty = tid >> 4;
    const int tx4 = tx << 2, ty4 = ty << 2;
    const int lrow = tid >> 2;           // 0..63
    const int ldb  = (tid & 3) << 4;     // 0,16,32,48

    // Load & transpose Q (pre-scaled by 1/sqrt(D) = 0.125)
    const int qbase = (bh * T_ + q0) * D_;
    #pragma unroll
    for (int rep = 0; rep < 4; ++rep) {
        int d = ldb + rep * 4;
        float4 v = *(const float4*)&g_q[qbase + lrow * D_ + d];
        sQ[(d + 0) * APITCH + lrow] = v.x * 0.125f;
        sQ[(d + 1) * APITCH + lrow] = v.y * 0.125f;
        sQ[(d + 2) * APITCH + lrow] = v.z * 0.125f;
        sQ[(d + 3) * APITCH + lrow] = v.w * 0.125f;
    }

    float m_i[4], l_i[4], acc[4][4];
    #pragma unroll
    for (int i = 0; i < 4; ++i) {
        m_i[i] = -1e30f; l_i[i] = 0.0f;
        #pragma unroll
        for (int j = 0; j < 4; ++j) acc[i][j] = 0.0f;
    }

    for (int kt = 0; kt <= qt; ++kt) {
        __syncthreads();  // prior-iter P/V reads done; also fences sQ writes (iter 0)

        const int kbase = (bh * T_ + kt * 64) * D_;
        #pragma unroll
        for (int rep = 0; rep < 4; ++rep) {
            int d = ldb + rep * 4;
            float4 kv = *(const float4*)&g_k[kbase + lrow * D_ + d];
            sK[(d + 0) * APITCH + lrow] = kv.x;
            sK[(d + 1) * APITCH + lrow] = kv.y;
            sK[(d + 2) * APITCH + lrow] = kv.z;
            sK[(d + 3) * APITCH + lrow] = kv.w;
            float4 vv = *(const float4*)&g_v[kbase + lrow * D_ + d];
            *(float4*)&sV[lrow * APITCH + d] = vv;
        }
        __syncthreads();

        // S = (Q * scale) @ K^T  (64x64, 4x4 per thread)
        float s[4][4];
        #pragma unroll
        for (int i = 0; i < 4; ++i)
            #pragma unroll
            for (int j = 0; j < 4; ++j) s[i][j] = 0.0f;

        #pragma unroll 8
        for (int d = 0; d < 64; ++d) {
            float4 q = *(const float4*)&sQ[d * APITCH + ty4];
            float4 k = *(const float4*)&sK[d * APITCH + tx4];
            s[0][0] += q.x * k.x; s[0][1] += q.x * k.y; s[0][2] += q.x * k.z; s[0][3] += q.x * k.w;
            s[1][0] += q.y * k.x; s[1][1] += q.y * k.y; s[1][2] += q.y * k.z; s[1][3] += q.y * k.w;
            s[2][0] += q.z * k.x; s[2][1] += q.z * k.y; s[2][2] += q.z * k.z; s[2][3] += q.z * k.w;
            s[3][0] += q.w * k.x; s[3][1] += q.w * k.y; s[3][2] += q.w * k.z; s[3][3] += q.w * k.w;
        }

        // Causal mask on the diagonal tile (q0 == k0 there)
        if (kt == qt) {
            #pragma unroll
            for (int i = 0; i < 4; ++i)
                #pragma unroll
                for (int j = 0; j < 4; ++j)
                    if (tx4 + j > ty4 + i) s[i][j] = -1e30f;
        }

        // Online softmax update (row reductions across the 16 tx lanes)
        #pragma unroll
        for (int i = 0; i < 4; ++i) {
            float rmax = fmaxf(fmaxf(s[i][0], s[i][1]), fmaxf(s[i][2], s[i][3]));
            #pragma unroll
            for (int o = 8; o > 0; o >>= 1)
                rmax = fmaxf(rmax, __shfl_xor_sync(0xffffffffu, rmax, o));
            float mn = fmaxf(m_i[i], rmax);
            float alpha = __expf(m_i[i] - mn);
            m_i[i] = mn;
            float rsum = 0.0f;
            #pragma unroll
            for (int j = 0; j < 4; ++j) {
                s[i][j] = __expf(s[i][j] - mn);
                rsum += s[i][j];
            }
            #pragma unroll
            for (int o = 8; o > 0; o >>= 1)
                rsum += __shfl_xor_sync(0xffffffffu, rsum, o);
            l_i[i] = l_i[i] * alpha + rsum;
            #pragma unroll
            for (int j = 0; j < 4; ++j) acc[i][j] *= alpha;
        }

        __syncthreads();  // all threads done reading sK for S

        // Write P into sK as [k][r] (float4 contiguous in r)
        #pragma unroll
        for (int j = 0; j < 4; ++j) {
            float4 p = make_float4(s[0][j], s[1][j], s[2][j], s[3][j]);
            *(float4*)&sK[(tx4 + j) * APITCH + ty4] = p;
        }
        __syncthreads();

        // O += P @ V
        #pragma unroll 8
        for (int k = 0; k < 64; ++k) {
            float4 p = *(const float4*)&sK[k * APITCH + ty4];
            float4 v = *(const float4*)&sV[k * APITCH + tx4];
            acc[0][0] += p.x * v.x; acc[0][1] += p.x * v.y; acc[0][2] += p.x * v.z; acc[0][3] += p.x * v.w;
            acc[1][0] += p.y * v.x; acc[1][1] += p.y * v.y; acc[1][2] += p.y * v.z; acc[1][3] += p.y * v.w;
            acc[2][0] += p.z * v.x; acc[2][1] += p.z * v.y; acc[2][2] += p.z * v.z; acc[2][3] += p.z * v.w;
            acc[3][0] += p.w * v.x; acc[3][1] += p.w * v.y; acc[3][2] += p.w * v.z; acc[3][3] += p.w * v.w;
        }
    }

    // Epilogue: y[b, t, h*64 + c] = acc / l
    #pragma unroll
    for (int i = 0; i < 4; ++i) {
        float inv = 1.0f / l_i[i];
        float4 o = make_float4(acc[i][0] * inv, acc[i][1] * inv,
                               acc[i][2] * inv, acc[i][3] * inv);
        int row = b * T_ + q0 + ty4 + i;
        *(float4*)&g_y[row * C_ + h * D_ + tx4] = o;
    }
}

// ---------------------------------------------------------------------------
extern "C" void kernel_launch(void* const* d_in, const int* in_sizes, int n_in,
                              void* d_out, int out_size)
{
    const float* x      = (const float*)d_in[0];
    const float* w_attn = (const float*)d_in[1];
    const float* b_attn = (const float*)d_in[2];
    const float* w_proj = (const float*)d_in[3];
    const float* b_proj = (const float*)d_in[4];
    float* out = (float*)d_out;

    cudaFuncSetAttribute(attn_kernel,
                         cudaFuncAttributeMaxDynamicSharedMemorySize, ATT_SMEM);

    gemm_qkv_kernel<<<dim3(N3_ / 64, M_ / 64), 256>>>(x, w_attn, b_attn);
    attn_kernel<<<dim3(T_ / 64, BH_), 256, ATT_SMEM>>>();
    gemm_proj_kernel<<<dim3(C_ / 64, M_ / 64), 256>>>(w_proj, b_proj, out);
}

// round 2
// speedup vs baseline: 2.2869x; 2.2869x over previous
#include <cuda_runtime.h>

#define B_   4
#define T_   2048
#define C_   768
#define H_   12
#define D_   64
#define BH_  48
#define M_   8192
#define N3_  2304

// ---- scratch (device globals; no runtime allocation) ----
__device__ float g_xr[M_ * C_];      // x rounded to tf32
__device__ float g_wat[N3_ * C_];    // w_attn^T  [2304][768] tf32
__device__ float g_wpt[C_ * C_];     // w_proj^T  [768][768]  tf32
__device__ float g_q[BH_ * T_ * D_]; // [bh][t][d], pre-scaled by 0.125, tf32
__device__ float g_k[BH_ * T_ * D_]; // [bh][t][d] tf32
__device__ float g_vt[BH_ * D_ * T_];// [bh][d][t] tf32 (transposed)
__device__ float g_y[M_ * C_];       // attention out [m][c] tf32

__device__ __forceinline__ float rna(float x) {
    unsigned r; asm("cvt.rna.tf32.f32 %0, %1;" : "=r"(r) : "f"(x));
    return __uint_as_float(r);
}
__device__ __forceinline__ unsigned fau(float x) { return __float_as_uint(x); }

__device__ __forceinline__ void mma8(float* c,
    unsigned a0, unsigned a1, unsigned a2, unsigned a3,
    unsigned b0, unsigned b1)
{
    asm volatile(
      "mma.sync.aligned.m16n8k8.row.col.f32.tf32.tf32.f32 "
      "{%0,%1,%2,%3},{%4,%5,%6,%7},{%8,%9},{%0,%1,%2,%3};"
      : "+f"(c[0]), "+f"(c[1]), "+f"(c[2]), "+f"(c[3])
      : "r"(a0), "r"(a1), "r"(a2), "r"(a3), "r"(b0), "r"(b1));
}

// ---------------------------------------------------------------------------
// Prep: round x to tf32
// ---------------------------------------------------------------------------
__global__ void round_kernel(const float* __restrict__ in, float* __restrict__ out, int n4)
{
    for (int i = blockIdx.x * blockDim.x + threadIdx.x; i < n4; i += gridDim.x * blockDim.x) {
        float4 v = ((const float4*)in)[i];
        v.x = rna(v.x); v.y = rna(v.y); v.z = rna(v.z); v.w = rna(v.w);
        ((float4*)out)[i] = v;
    }
}

// Prep: transpose + round. in [R][Cc] -> out [Cc][R]
__global__ void transpose_round_kernel(const float* __restrict__ in, float* __restrict__ out,
                                       int R, int Cc)
{
    __shared__ float tile[32][33];
    int bx = blockIdx.x * 32;   // col block
    int by = blockIdx.y * 32;   // row block
    int x = bx + threadIdx.x;
    #pragma unroll
    for (int j = threadIdx.y; j < 32; j += 8)
        tile[j][threadIdx.x] = in[(by + j) * Cc + x];
    __syncthreads();
    int ox = by + threadIdx.x;
    #pragma unroll
    for (int j = threadIdx.y; j < 32; j += 8)
        out[(bx + j) * R + ox] = rna(tile[threadIdx.x][j]);
}

// ---------------------------------------------------------------------------
// tf32 GEMM: C[128x64 tile] = A[m][k=768] @ Bt[n][k=768]^T (+bias)
// mode 0: QKV epilogue (scatter to g_q (x0.125) / g_k / g_vt transposed)
// mode 1: plain epilogue to out (fp32)
// 256 threads = 8 warps (4m x 2n), warp tile 32x32, k-step 32, reg prefetch.
// ---------------------------------------------------------------------------
__global__ __launch_bounds__(256) void gemm_kernel(
    const float* __restrict__ A, const float* __restrict__ Bt,
    const float* __restrict__ bias, float* __restrict__ out, int mode)
{
    __shared__ float sA[128 * 36];
    __shared__ float sB[64 * 36];

    const int m0 = blockIdx.y * 128;
    const int n0 = blockIdx.x * 64;
    const int tid = threadIdx.x;
    const int warp = tid >> 5, lane = tid & 31;
    const int g = lane >> 2, tig = lane & 3;
    const int wm = warp & 3, wn = warp >> 2;

    const int arow = tid >> 1, acol = (tid & 1) * 16;  // 4 float4
    const int brow = tid >> 2, bcol = (tid & 3) * 8;   // 2 float4

    const float* Ab = A + (long)(m0 + arow) * C_ + acol;
    const float* Bb = Bt + (long)(n0 + brow) * C_ + bcol;

    float acc[2][4][4];
    #pragma unroll
    for (int mf = 0; mf < 2; ++mf)
        #pragma unroll
        for (int nf = 0; nf < 4; ++nf)
            #pragma unroll
            for (int e = 0; e < 4; ++e) acc[mf][nf][e] = 0.0f;

    float4 pa[4], pb[2];
    #pragma unroll
    for (int j = 0; j < 4; ++j) pa[j] = *(const float4*)(Ab + j * 4);
    #pragma unroll
    for (int j = 0; j < 2; ++j) pb[j] = *(const float4*)(Bb + j * 4);
    #pragma unroll
    for (int j = 0; j < 4; ++j) *(float4*)(sA + arow * 36 + acol + j * 4) = pa[j];
    #pragma unroll
    for (int j = 0; j < 2; ++j) *(float4*)(sB + brow * 36 + bcol + j * 4) = pb[j];
    __syncthreads();

    const int NSTEP = C_ / 32;  // 24
    for (int ks = 0; ks < NSTEP; ++ks) {
        if (ks + 1 < NSTEP) {
            int k1 = (ks + 1) * 32;
            #pragma unroll
            for (int j = 0; j < 4; ++j) pa[j] = *(const float4*)(Ab + k1 + j * 4);
            #pragma unroll
            for (int j = 0; j < 2; ++j) pb[j] = *(const float4*)(Bb + k1 + j * 4);
        }
        #pragma unroll
        for (int kf = 0; kf < 4; ++kf) {
            unsigned a[2][4];
            #pragma unroll
            for (int mf = 0; mf < 2; ++mf) {
                const float* q = sA + (wm * 32 + mf * 16) * 36 + kf * 8 + tig;
                a[mf][0] = fau(q[g * 36]);
                a[mf][1] = fau(q[(g + 8) * 36]);
                a[mf][2] = fau(q[g * 36 + 4]);
                a[mf][3] = fau(q[(g + 8) * 36 + 4]);
            }
            #pragma unroll
            for (int nf = 0; nf < 4; ++nf) {
                const float* kp = sB + (wn * 32 + nf * 8 + g) * 36 + kf * 8 + tig;
                unsigned b0 = fau(kp[0]);
                unsigned b1 = fau(kp[4]);
                mma8(acc[0][nf], a[0][0], a[0][1], a[0][2], a[0][3], b0, b1);
                mma8(acc[1][nf], a[1][0], a[1][1], a[1][2], a[1][3], b0, b1);
            }
        }
        __syncthreads();
        if (ks + 1 < NSTEP) {
            #pragma unroll
            for (int j = 0; j < 4; ++j) *(float4*)(sA + arow * 36 + acol + j * 4) = pa[j];
            #pragma unroll
            for (int j = 0; j < 2; ++j) *(float4*)(sB + brow * 36 + bcol + j * 4) = pb[j];
            __syncthreads();
        }
    }

    if (mode == 1) {
        // plain: out[m][n] = acc + bias (fp32 final output)
        #pragma unroll
        for (int mf = 0; mf < 2; ++mf) {
            int r = m0 + wm * 32 + mf * 16 + g;
            #pragma unroll
            for (int nf = 0; nf < 4; ++nf) {
                int c = n0 + wn * 32 + nf * 8 + 2 * tig;
                float bz0 = bias[c], bz1 = bias[c + 1];
                *(float2*)(out + (long)r * C_ + c) =
                    make_float2(acc[mf][nf][0] + bz0, acc[mf][nf][1] + bz1);
                *(float2*)(out + (long)(r + 8) * C_ + c) =
                    make_float2(acc[mf][nf][2] + bz0, acc[mf][nf][3] + bz1);
            }
        }
        return;
    }

    // QKV epilogue
    const int which = n0 / C_;          // 0=q,1=k,2=v
    const int hh = (n0 % C_) >> 6;      // head
    const int bb = m0 >> 11;            // batch
    const int t0 = m0 & (T_ - 1);
    const int bh = bb * H_ + hh;

    #pragma unroll
    for (int mf = 0; mf < 2; ++mf) {
        int t = t0 + wm * 32 + mf * 16 + g;
        #pragma unroll
        for (int nf = 0; nf < 4; ++nf) {
            int d = wn * 32 + nf * 8 + 2 * tig;
            float bz0 = bias[n0 + d], bz1 = bias[n0 + d + 1];
            float v0 = acc[mf][nf][0] + bz0, v1 = acc[mf][nf][1] + bz1;
            float v2 = acc[mf][nf][2] + bz0, v3 = acc[mf][nf][3] + bz1;
            if (which == 0) {
                *(float2*)(g_q + ((long)(bh)*T_ + t) * D_ + d) =
                    make_float2(rna(v0 * 0.125f), rna(v1 * 0.125f));
                *(float2*)(g_q + ((long)(bh)*T_ + t + 8) * D_ + d) =
                    make_float2(rna(v2 * 0.125f), rna(v3 * 0.125f));
            } else if (which == 1) {
                *(float2*)(g_k + ((long)(bh)*T_ + t) * D_ + d) =
                    make_float2(rna(v0), rna(v1));
                *(float2*)(g_k + ((long)(bh)*T_ + t + 8) * D_ + d) =
                    make_float2(rna(v2), rna(v3));
            } else {
                // transposed: g_vt[bh][d][t]
                float* base = g_vt + ((long)bh * D_ + d) * T_;
                base[t]            = rna(v0);
                base[T_ + t]       = rna(v1);
                base[t + 8]        = rna(v2);
                base[T_ + t + 8]   = rna(v3);
            }
        }
    }
}

// ---------------------------------------------------------------------------
// Flash attention, tf32 mma. Block = 128 queries x one (b,h), 4 warps.
// Warp w owns rows w*32..w*32+31 (2 m16 frags). K/V tile = 64.
// ---------------------------------------------------------------------------
#define ATT_SMEM ((128 + 64 + 64 + 128) * 68 * 4)

__global__ __launch_bounds__(128) void attn_kernel()
{
    extern __shared__ float sm[];
    float* sQ  = sm;                 // [128][68]
    float* sK  = sQ + 128 * 68;      // [64][68]
    float* sVt = sK + 64 * 68;       // [64][68]  (d rows, t cols)
    float* sP  = sVt + 64 * 68;      // [128][68]

    const int qb = blockIdx.x;       // 0..15
    const int bh = blockIdx.y;       // 0..47
    const int bb = bh / H_, hh = bh % H_;
    const int q0 = qb * 128;
    const int tid = threadIdx.x;
    const int warp = tid >> 5, lane = tid & 31;
    const int g = lane >> 2, tig = lane & 3;

    // Load Q tile (already scaled & rounded)
    {
        const float* src = g_q + ((long)bh * T_ + q0 + tid) * D_;
        float* dst = sQ + tid * 68;
        #pragma unroll
        for (int j = 0; j < 16; ++j)
            *(float4*)(dst + j * 4) = *(const float4*)(src + j * 4);
    }

    float oacc[2][8][4];
    float mst[2][2], lst[2][2];
    #pragma unroll
    for (int mf = 0; mf < 2; ++mf) {
        mst[mf][0] = -1e30f; mst[mf][1] = -1e30f;
        lst[mf][0] = 0.0f;   lst[mf][1] = 0.0f;
        #pragma unroll
        for (int nt = 0; nt < 8; ++nt)
            #pragma unroll
            for (int e = 0; e < 4; ++e) oacc[mf][nt][e] = 0.0f;
    }

    const int ktmax = 2 * qb + 1;
    for (int kt = 0; kt <= ktmax; ++kt) {
        __syncthreads();
        {
            int r = tid >> 1, cb = (tid & 1) * 32;
            const float* ksrc = g_k + ((long)bh * T_ + kt * 64 + r) * D_ + cb;
            float* kdst = sK + r * 68 + cb;
            #pragma unroll
            for (int j = 0; j < 8; ++j)
                *(float4*)(kdst + j * 4) = *(const float4*)(ksrc + j * 4);
            const float* vsrc = g_vt + ((long)bh * D_ + r) * T_ + kt * 64 + cb;
            float* vdst = sVt + r * 68 + cb;
            #pragma unroll
            for (int j = 0; j < 8; ++j)
                *(float4*)(vdst + j * 4) = *(const float4*)(vsrc + j * 4);
        }
        __syncthreads();

        // S = Q @ K^T  (per warp: 32 x 64)
        float sacc[2][8][4];
        #pragma unroll
        for (int mf = 0; mf < 2; ++mf)
            #pragma unroll
            for (int nt = 0; nt < 8; ++nt)
                #pragma unroll
                for (int e = 0; e < 4; ++e) sacc[mf][nt][e] = 0.0f;

        #pragma unroll
        for (int kf = 0; kf < 8; ++kf) {
            unsigned a[2][4];
            #pragma unroll
            for (int mf = 0; mf < 2; ++mf) {
                const float* q = sQ + (warp * 32 + mf * 16) * 68 + kf * 8 + tig;
                a[mf][0] = fau(q[g * 68]);
                a[mf][1] = fau(q[(g + 8) * 68]);
                a[mf][2] = fau(q[g * 68 + 4]);
                a[mf][3] = fau(q[(g + 8) * 68 + 4]);
            }
            #pragma unroll
            for (int nt = 0; nt < 8; ++nt) {
                const float* kp = sK + (nt * 8 + g) * 68 + kf * 8 + tig;
                unsigned b0 = fau(kp[0]);
                unsigned b1 = fau(kp[4]);
                mma8(sacc[0][nt], a[0][0], a[0][1], a[0][2], a[0][3], b0, b1);
                mma8(sacc[1][nt], a[1][0], a[1][1], a[1][2], a[1][3], b0, b1);
            }
        }

        const bool dmask = (kt >= 2 * qb);
        #pragma unroll
        for (int mf = 0; mf < 2; ++mf) {
            const int rbase = q0 + warp * 32 + mf * 16 + g;
            if (dmask) {
                #pragma unroll
                for (int nt = 0; nt < 8; ++nt) {
                    int cb = kt * 64 + nt * 8 + 2 * tig;
                    if (cb     > rbase)     sacc[mf][nt][0] = -1e30f;
                    if (cb + 1 > rbase)     sacc[mf][nt][1] = -1e30f;
                    if (cb     > rbase + 8) sacc[mf][nt][2] = -1e30f;
                    if (cb + 1 > rbase + 8) sacc[mf][nt][3] = -1e30f;
                }
            }
            float mx0 = -1e30f, mx1 = -1e30f;
            #pragma unroll
            for (int nt = 0; nt < 8; ++nt) {
                mx0 = fmaxf(mx0, fmaxf(sacc[mf][nt][0], sacc[mf][nt][1]));
                mx1 = fmaxf(mx1, fmaxf(sacc[mf][nt][2], sacc[mf][nt][3]));
            }
            mx0 = fmaxf(mx0, __shfl_xor_sync(0xffffffffu, mx0, 1));
            mx0 = fmaxf(mx0, __shfl_xor_sync(0xffffffffu, mx0, 2));
            mx1 = fmaxf(mx1, __shfl_xor_sync(0xffffffffu, mx1, 1));
            mx1 = fmaxf(mx1, __shfl_xor_sync(0xffffffffu, mx1, 2));

            float mn0 = fmaxf(mst[mf][0], mx0);
            float mn1 = fmaxf(mst[mf][1], mx1);
            float al0 = __expf(mst[mf][0] - mn0);
            float al1 = __expf(mst[mf][1] - mn1);
            mst[mf][0] = mn0; mst[mf][1] = mn1;

            float sum0 = 0.0f, sum1 = 0.0f;
            const int prow = warp * 32 + mf * 16 + g;
            #pragma unroll
            for (int nt = 0; nt < 8; ++nt) {
                float p0 = __expf(sacc[mf][nt][0] - mn0);
                float p1 = __expf(sacc[mf][nt][1] - mn0);
                float p2 = __expf(sacc[mf][nt][2] - mn1);
                float p3 = __expf(sacc[mf][nt][3] - mn1);
                sum0 += p0 + p1;
                sum1 += p2 + p3;
                *(float2*)(sP + prow * 68 + nt * 8 + 2 * tig) =
                    make_float2(rna(p0), rna(p1));
                *(float2*)(sP + (prow + 8) * 68 + nt * 8 + 2 * tig) =
                    make_float2(rna(p2), rna(p3));
            }
            sum0 += __shfl_xor_sync(0xffffffffu, sum0, 1);
            sum0 += __shfl_xor_sync(0xffffffffu, sum0, 2);
            sum1 += __shfl_xor_sync(0xffffffffu, sum1, 1);
            sum1 += __shfl_xor_sync(0xffffffffu, sum1, 2);
            lst[mf][0] = lst[mf][0] * al0 + sum0;
            lst[mf][1] = lst[mf][1] * al1 + sum1;

            #pragma unroll
            for (int nt = 0; nt < 8; ++nt) {
                oacc[mf][nt][0] *= al0;
                oacc[mf][nt][1] *= al0;
                oacc[mf][nt][2] *= al1;
                oacc[mf][nt][3] *= al1;
            }
        }
        __syncwarp();

        // O += P @ V
        #pragma unroll
        for (int kf = 0; kf < 8; ++kf) {
            unsigned a[2][4];
            #pragma unroll
            for (int mf = 0; mf < 2; ++mf) {
                const float* pp = sP + (warp * 32 + mf * 16) * 68 + kf * 8 + tig;
                a[mf][0] = fau(pp[g * 68]);
                a[mf][1] = fau(pp[(g + 8) * 68]);
                a[mf][2] = fau(pp[g * 68 + 4]);
                a[mf][3] = fau(pp[(g + 8) * 68 + 4]);
            }
            #pragma unroll
            for (int nt = 0; nt < 8; ++nt) {
                const float* vp = sVt + (nt * 8 + g) * 68 + kf * 8 + tig;
                unsigned b0 = fau(vp[0]);
                unsigned b1 = fau(vp[4]);
                mma8(oacc[0][nt], a[0][0], a[0][1], a[0][2], a[0][3], b0, b1);
                mma8(oacc[1][nt], a[1][0], a[1][1], a[1][2], a[1][3], b0, b1);
            }
        }
    }

    // Epilogue: y[b*T + row][h*64 + col] = O / l, tf32-rounded for proj GEMM
    #pragma unroll
    for (int mf = 0; mf < 2; ++mf) {
        int row = q0 + warp * 32 + mf * 16 + g;
        float inv0 = 1.0f / lst[mf][0];
        float inv1 = 1.0f / lst[mf][1];
        #pragma unroll
        for (int nt = 0; nt < 8; ++nt) {
            int col = hh * 64 + nt * 8 + 2 * tig;
            *(float2*)(g_y + ((long)bb * T_ + row) * C_ + col) =
                make_float2(rna(oacc[mf][nt][0] * inv0), rna(oacc[mf][nt][1] * inv0));
            *(float2*)(g_y + ((long)bb * T_ + row + 8) * C_ + col) =
                make_float2(rna(oacc[mf][nt][2] * inv1), rna(oacc[mf][nt][3] * inv1));
        }
    }
}

// ---------------------------------------------------------------------------
extern "C" void kernel_launch(void* const* d_in, const int* in_sizes, int n_in,
                              void* d_out, int out_size)
{
    const float* x      = (const float*)d_in[0];
    const float* w_attn = (const float*)d_in[1];
    const float* b_attn = (const float*)d_in[2];
    const float* w_proj = (const float*)d_in[3];
    const float* b_proj = (const float*)d_in[4];
    float* out = (float*)d_out;

    float *xr, *wat, *wpt, *yy;
    cudaGetSymbolAddress((void**)&xr,  g_xr);
    cudaGetSymbolAddress((void**)&wat, g_wat);
    cudaGetSymbolAddress((void**)&wpt, g_wpt);
    cudaGetSymbolAddress((void**)&yy,  g_y);

    cudaFuncSetAttribute(attn_kernel,
                         cudaFuncAttributeMaxDynamicSharedMemorySize, ATT_SMEM);

    round_kernel<<<512, 256>>>(x, xr, M_ * C_ / 4);
    transpose_round_kernel<<<dim3(N3_ / 32, C_ / 32), dim3(32, 8)>>>(w_attn, wat, C_, N3_);
    transpose_round_kernel<<<dim3(C_ / 32, C_ / 32), dim3(32, 8)>>>(w_proj, wpt, C_, C_);

    gemm_kernel<<<dim3(N3_ / 64, M_ / 128), 256>>>(xr, wat, b_attn, nullptr, 0);
    attn_kernel<<<dim3(T_ / 128, BH_), 128, ATT_SMEM>>>();
    gemm_kernel<<<dim3(C_ / 64, M_ / 128), 256>>>(yy, wpt, b_proj, out, 1);
}

// round 3
// speedup vs baseline: 2.6757x; 1.1700x over previous
#include <cuda_runtime.h>

#define B_   4
#define T_   2048
#define C_   768
#define H_   12
#define D_   64
#define BH_  48
#define M_   8192
#define N3_  2304

// ---- scratch (device globals) ----
__device__ float g_wat[N3_ * C_];    // w_attn^T [2304][768] tf32
__device__ float g_wpt[C_ * C_];     // w_proj^T [768][768]  tf32
__device__ float g_q[BH_ * T_ * D_]; // [bh][t][d] *0.125, tf32
__device__ float g_k[BH_ * T_ * D_]; // [bh][t][d] tf32
__device__ float g_vt[BH_ * D_ * T_];// [bh][d][t] tf32
__device__ float g_y[M_ * C_];       // attn out, tf32

__device__ __forceinline__ float rna(float x) {
    unsigned r; asm("cvt.rna.tf32.f32 %0, %1;" : "=r"(r) : "f"(x));
    return __uint_as_float(r);
}
__device__ __forceinline__ unsigned fau(float x) { return __float_as_uint(x); }

__device__ __forceinline__ void mma8(float* c,
    unsigned a0, unsigned a1, unsigned a2, unsigned a3,
    unsigned b0, unsigned b1)
{
    asm volatile(
      "mma.sync.aligned.m16n8k8.row.col.f32.tf32.tf32.f32 "
      "{%0,%1,%2,%3},{%4,%5,%6,%7},{%8,%9},{%0,%1,%2,%3};"
      : "+f"(c[0]), "+f"(c[1]), "+f"(c[2]), "+f"(c[3])
      : "r"(a0), "r"(a1), "r"(a2), "r"(a3), "r"(b0), "r"(b1));
}

// ---------------------------------------------------------------------------
// Prep: transpose + round to tf32. in [R][Cc] -> out [Cc][R]
// ---------------------------------------------------------------------------
__global__ void transpose_round_kernel(const float* __restrict__ in, float* __restrict__ out,
                                       int R, int Cc)
{
    __shared__ float tile[32][33];
    int bx = blockIdx.x * 32, by = blockIdx.y * 32;
    int x = bx + threadIdx.x;
    #pragma unroll
    for (int j = threadIdx.y; j < 32; j += 8)
        tile[j][threadIdx.x] = in[(by + j) * Cc + x];
    __syncthreads();
    int ox = by + threadIdx.x;
    #pragma unroll
    for (int j = threadIdx.y; j < 32; j += 8)
        out[(bx + j) * R + ox] = rna(tile[threadIdx.x][j]);
}

// ---------------------------------------------------------------------------
// tf32 GEMM, block 128x128, 8 warps (4m x 2n), warp tile 32x64, k-step 32,
// permuted-k smem (LDS.64 fragments), double-buffered.
// mode 0: QKV scatter epilogue; mode 1: plain epilogue (fp32 + bias).
// ---------------------------------------------------------------------------
#define GP 40              // smem pitch (floats), 40 % 32 == 8 -> conflict-free frags
#define GA (128 * GP)      // one buffer, floats
#define GEMM_SMEM (4 * GA * 4)   // 2 bufs x (A+B) = 81920 B

__global__ __launch_bounds__(256, 2) void gemm_kernel(
    const float* __restrict__ A, const float* __restrict__ Bt,
    const float* __restrict__ bias, float* __restrict__ out, int mode)
{
    extern __shared__ float sm[];
    float* sAb = sm;            // 2 buffers
    float* sBb = sm + 2 * GA;   // 2 buffers

    const int m0 = blockIdx.y * 128;
    const int n0 = blockIdx.x * 128;
    const int tid = threadIdx.x;
    const int warp = tid >> 5, lane = tid & 31;
    const int g = lane >> 2, tig = lane & 3;
    const int wm = warp & 3, wn = warp >> 2;

    const int srow = tid >> 1;          // 0..127
    const int scol = (tid & 1) * 16;    // 0 or 16

    const float* Ap = A  + (long)(m0 + srow) * C_ + scol;
    const float* Bp = Bt + (long)(n0 + srow) * C_ + scol;

    float acc[2][8][4] = {};
    float4 pa[4], pb[4];

    // prologue load + stage
    #pragma unroll
    for (int j = 0; j < 4; ++j) { pa[j] = *(const float4*)(Ap + j * 4);
                                  pb[j] = *(const float4*)(Bp + j * 4); }
    {
        float* dA = sAb + srow * GP;
        float* dB = sBb + srow * GP;
        #pragma unroll
        for (int gi = 0; gi < 2; ++gi) {
            const float* f0 = (const float*)&pa[2 * gi];
            const float* f1 = (const float*)&pa[2 * gi + 1];
            const float* h0 = (const float*)&pb[2 * gi];
            const float* h1 = (const float*)&pb[2 * gi + 1];
            int base = scol + gi * 8;
            #pragma unroll
            for (int t = 0; t < 4; ++t) {
                *(float2*)(dA + base + 2 * t) = make_float2(rna(f0[t]), rna(f1[t]));
                *(float2*)(dB + base + 2 * t) = make_float2(h0[t], h1[t]);
            }
        }
    }
    __syncthreads();

    const int NS = C_ / 32;  // 24
    for (int ks = 0; ks < NS; ++ks) {
        const int buf = ks & 1;
        if (ks + 1 < NS) {
            int k1 = (ks + 1) * 32;
            #pragma unroll
            for (int j = 0; j < 4; ++j) { pa[j] = *(const float4*)(Ap + k1 + j * 4);
                                          pb[j] = *(const float4*)(Bp + k1 + j * 4); }
        }
        const float* cA = sAb + buf * GA;
        const float* cB = sBb + buf * GA;
        #pragma unroll
        for (int kf = 0; kf < 4; ++kf) {
            unsigned a[2][4];
            #pragma unroll
            for (int mf = 0; mf < 2; ++mf) {
                const float* p = cA + (wm * 32 + mf * 16) * GP + kf * 8 + 2 * tig;
                float2 x0 = *(const float2*)(p + g * GP);
                float2 x1 = *(const float2*)(p + (g + 8) * GP);
                a[mf][0] = fau(x0.x); a[mf][1] = fau(x1.x);
                a[mf][2] = fau(x0.y); a[mf][3] = fau(x1.y);
            }
            #pragma unroll
            for (int nt = 0; nt < 8; ++nt) {
                float2 bv = *(const float2*)(cB + (wn * 64 + nt * 8 + g) * GP + kf * 8 + 2 * tig);
                unsigned b0 = fau(bv.x), b1 = fau(bv.y);
                mma8(acc[0][nt], a[0][0], a[0][1], a[0][2], a[0][3], b0, b1);
                mma8(acc[1][nt], a[1][0], a[1][1], a[1][2], a[1][3], b0, b1);
            }
        }
        if (ks + 1 < NS) {
            float* dA = sAb + (buf ^ 1) * GA + srow * GP;
            float* dB = sBb + (buf ^ 1) * GA + srow * GP;
            #pragma unroll
            for (int gi = 0; gi < 2; ++gi) {
                const float* f0 = (const float*)&pa[2 * gi];
                const float* f1 = (const float*)&pa[2 * gi + 1];
                const float* h0 = (const float*)&pb[2 * gi];
                const float* h1 = (const float*)&pb[2 * gi + 1];
                int base = scol + gi * 8;
                #pragma unroll
                for (int t = 0; t < 4; ++t) {
                    *(float2*)(dA + base + 2 * t) = make_float2(rna(f0[t]), rna(f1[t]));
                    *(float2*)(dB + base + 2 * t) = make_float2(h0[t], h1[t]);
                }
            }
        }
        __syncthreads();
    }

    if (mode == 1) {
        #pragma unroll
        for (int mf = 0; mf < 2; ++mf) {
            int r = m0 + wm * 32 + mf * 16 + g;
            #pragma unroll
            for (int nt = 0; nt < 8; ++nt) {
                int c = n0 + wn * 64 + nt * 8 + 2 * tig;
                float b0 = bias[c], b1 = bias[c + 1];
                *(float2*)(out + (long)r * C_ + c) =
                    make_float2(acc[mf][nt][0] + b0, acc[mf][nt][1] + b1);
                *(float2*)(out + (long)(r + 8) * C_ + c) =
                    make_float2(acc[mf][nt][2] + b0, acc[mf][nt][3] + b1);
            }
        }
        return;
    }

    // QKV scatter epilogue (each warp's 64-wide n-range = exactly one head)
    const int ncw   = n0 + wn * 64;
    const int which = ncw / C_;
    const int hh    = (ncw % C_) >> 6;
    const int bb    = m0 >> 11;
    const int t0    = m0 & (T_ - 1);
    const int bh    = bb * H_ + hh;

    #pragma unroll
    for (int mf = 0; mf < 2; ++mf) {
        int t = t0 + wm * 32 + mf * 16 + g;
        #pragma unroll
        for (int nt = 0; nt < 8; ++nt) {
            int d = nt * 8 + 2 * tig;
            float b0 = bias[ncw + d], b1 = bias[ncw + d + 1];
            float v0 = acc[mf][nt][0] + b0, v1 = acc[mf][nt][1] + b1;
            float v2 = acc[mf][nt][2] + b0, v3 = acc[mf][nt][3] + b1;
            if (which == 0) {
                *(float2*)(g_q + ((long)bh * T_ + t) * D_ + d) =
                    make_float2(rna(v0 * 0.125f), rna(v1 * 0.125f));
                *(float2*)(g_q + ((long)bh * T_ + t + 8) * D_ + d) =
                    make_float2(rna(v2 * 0.125f), rna(v3 * 0.125f));
            } else if (which == 1) {
                *(float2*)(g_k + ((long)bh * T_ + t) * D_ + d) = make_float2(rna(v0), rna(v1));
                *(float2*)(g_k + ((long)bh * T_ + t + 8) * D_ + d) = make_float2(rna(v2), rna(v3));
            } else {
                float* bp = g_vt + ((long)bh * D_ + d) * T_;
                bp[t]          = rna(v0);
                bp[T_ + t]     = rna(v1);
                bp[t + 8]      = rna(v2);
                bp[T_ + t + 8] = rna(v3);
            }
        }
    }
}

// ---------------------------------------------------------------------------
// Flash attention: 8 warps x 16 query rows = 128 queries/block, K-tile 64.
// Q lives in registers; smem = K, V^T, P (all permuted-k, pitch 72).
// ---------------------------------------------------------------------------
#define AP 72
#define AK (64 * AP)
#define ATT_SMEM ((2 * AK + 128 * AP) * 4)   // 73728 B

__global__ __launch_bounds__(256, 2) void attn_kernel()
{
    extern __shared__ float sm[];
    float* sK = sm;
    float* sV = sm + AK;
    float* sP = sm + 2 * AK;

    const int qb = blockIdx.x;
    const int bh = blockIdx.y;
    const int bb = bh / H_, hh = bh % H_;
    const int q0 = qb * 128;
    const int tid = threadIdx.x;
    const int warp = tid >> 5, lane = tid & 31;
    const int g = lane >> 2, tig = lane & 3;

    const int srow = tid >> 2;         // 0..63
    const int scol = (tid & 3) * 16;   // 0,16,32,48

    // Q fragments in registers (already *0.125 and tf32-rounded)
    unsigned qf[8][4];
    {
        const float* r0 = g_q + ((long)bh * T_ + q0 + warp * 16 + g) * D_;
        const float* r1 = r0 + 8 * D_;
        #pragma unroll
        for (int kf = 0; kf < 8; ++kf) {
            qf[kf][0] = fau(r0[kf * 8 + tig]);
            qf[kf][1] = fau(r1[kf * 8 + tig]);
            qf[kf][2] = fau(r0[kf * 8 + tig + 4]);
            qf[kf][3] = fau(r1[kf * 8 + tig + 4]);
        }
    }

    float oacc[8][4] = {};
    float m0s = -1e30f, m1s = -1e30f, l0s = 0.0f, l1s = 0.0f;

    // P slot positions for accumulator cols 2tig, 2tig+1 (permuted layout)
    const int c0 = 2 * tig, c1 = 2 * tig + 1;
    const int s0 = (c0 & 3) * 2 + (c0 >> 2);
    const int s1 = (c1 & 3) * 2 + (c1 >> 2);
    const int prow = warp * 16 + g;

    const int ktmax = 2 * qb + 1;
    for (int kt = 0; kt <= ktmax; ++kt) {
        __syncthreads();
        {   // stage K [key][d-perm], V^T [d][key-perm]
            const float* ksrc = g_k  + ((long)bh * T_ + kt * 64 + srow) * D_ + scol;
            const float* vsrc = g_vt + ((long)bh * D_ + srow) * T_ + kt * 64 + scol;
            float4 kv[4], vv[4];
            #pragma unroll
            for (int j = 0; j < 4; ++j) { kv[j] = *(const float4*)(ksrc + j * 4);
                                          vv[j] = *(const float4*)(vsrc + j * 4); }
            float* kd = sK + srow * AP;
            float* vd = sV + srow * AP;
            #pragma unroll
            for (int gi = 0; gi < 2; ++gi) {
                const float* f0 = (const float*)&kv[2 * gi];
                const float* f1 = (const float*)&kv[2 * gi + 1];
                const float* h0 = (const float*)&vv[2 * gi];
                const float* h1 = (const float*)&vv[2 * gi + 1];
                int base = scol + gi * 8;
                #pragma unroll
                for (int t = 0; t < 4; ++t) {
                    *(float2*)(kd + base + 2 * t) = make_float2(f0[t], f1[t]);
                    *(float2*)(vd + base + 2 * t) = make_float2(h0[t], h1[t]);
                }
            }
        }
        __syncthreads();

        // S = Q @ K^T (warp: 16 x 64)
        float sacc[8][4] = {};
        #pragma unroll
        for (int kf = 0; kf < 8; ++kf) {
            #pragma unroll
            for (int nt = 0; nt < 8; ++nt) {
                float2 bv = *(const float2*)(sK + (nt * 8 + g) * AP + kf * 8 + 2 * tig);
                mma8(sacc[nt], qf[kf][0], qf[kf][1], qf[kf][2], qf[kf][3],
                     fau(bv.x), fau(bv.y));
            }
        }

        // causal mask on diagonal tiles
        const int rbase = q0 + warp * 16 + g;
        if (kt >= 2 * qb) {
            #pragma unroll
            for (int nt = 0; nt < 8; ++nt) {
                int cb = kt * 64 + nt * 8 + 2 * tig;
                if (cb     > rbase)     sacc[nt][0] = -1e30f;
                if (cb + 1 > rbase)     sacc[nt][1] = -1e30f;
                if (cb     > rbase + 8) sacc[nt][2] = -1e30f;
                if (cb + 1 > rbase + 8) sacc[nt][3] = -1e30f;
            }
        }

        // online softmax
        float mx0 = -1e30f, mx1 = -1e30f;
        #pragma unroll
        for (int nt = 0; nt < 8; ++nt) {
            mx0 = fmaxf(mx0, fmaxf(sacc[nt][0], sacc[nt][1]));
            mx1 = fmaxf(mx1, fmaxf(sacc[nt][2], sacc[nt][3]));
        }
        mx0 = fmaxf(mx0, __shfl_xor_sync(0xffffffffu, mx0, 1));
        mx0 = fmaxf(mx0, __shfl_xor_sync(0xffffffffu, mx0, 2));
        mx1 = fmaxf(mx1, __shfl_xor_sync(0xffffffffu, mx1, 1));
        mx1 = fmaxf(mx1, __shfl_xor_sync(0xffffffffu, mx1, 2));

        float mn0 = fmaxf(m0s, mx0), mn1 = fmaxf(m1s, mx1);
        float al0 = __expf(m0s - mn0), al1 = __expf(m1s - mn1);
        m0s = mn0; m1s = mn1;

        float sum0 = 0.0f, sum1 = 0.0f;
        #pragma unroll
        for (int nt = 0; nt < 8; ++nt) {
            float p0 = __expf(sacc[nt][0] - mn0);
            float p1 = __expf(sacc[nt][1] - mn0);
            float p2 = __expf(sacc[nt][2] - mn1);
            float p3 = __expf(sacc[nt][3] - mn1);
            sum0 += p0 + p1; sum1 += p2 + p3;
            float* pr0 = sP + prow * AP + nt * 8;
            float* pr1 = sP + (prow + 8) * AP + nt * 8;
            pr0[s0] = rna(p0); pr0[s1] = rna(p1);
            pr1[s0] = rna(p2); pr1[s1] = rna(p3);
        }
        sum0 += __shfl_xor_sync(0xffffffffu, sum0, 1);
        sum0 += __shfl_xor_sync(0xffffffffu, sum0, 2);
        sum1 += __shfl_xor_sync(0xffffffffu, sum1, 1);
        sum1 += __shfl_xor_sync(0xffffffffu, sum1, 2);
        l0s = l0s * al0 + sum0;
        l1s = l1s * al1 + sum1;
        #pragma unroll
        for (int nt = 0; nt < 8; ++nt) {
            oacc[nt][0] *= al0; oacc[nt][1] *= al0;
            oacc[nt][2] *= al1; oacc[nt][3] *= al1;
        }
        __syncwarp();

        // O += P @ V
        #pragma unroll
        for (int kf = 0; kf < 8; ++kf) {
            const float* p = sP + (warp * 16) * AP + kf * 8 + 2 * tig;
            float2 x0 = *(const float2*)(p + g * AP);
            float2 x1 = *(const float2*)(p + (g + 8) * AP);
            unsigned a0 = fau(x0.x), a1 = fau(x1.x), a2 = fau(x0.y), a3 = fau(x1.y);
            #pragma unroll
            for (int nt = 0; nt < 8; ++nt) {
                float2 bv = *(const float2*)(sV + (nt * 8 + g) * AP + kf * 8 + 2 * tig);
                mma8(oacc[nt], a0, a1, a2, a3, fau(bv.x), fau(bv.y));
            }
        }
        __syncwarp();
    }

    // epilogue -> g_y (tf32-rounded)
    const int row = q0 + warp * 16 + g;
    const float inv0 = 1.0f / l0s, inv1 = 1.0f / l1s;
    #pragma unroll
    for (int nt = 0; nt < 8; ++nt) {
        int col = hh * 64 + nt * 8 + 2 * tig;
        *(float2*)(g_y + ((long)bb * T_ + row) * C_ + col) =
            make_float2(rna(oacc[nt][0] * inv0), rna(oacc[nt][1] * inv0));
        *(float2*)(g_y + ((long)bb * T_ + row + 8) * C_ + col) =
            make_float2(rna(oacc[nt][2] * inv1), rna(oacc[nt][3] * inv1));
    }
}

// ---------------------------------------------------------------------------
extern "C" void kernel_launch(void* const* d_in, const int* in_sizes, int n_in,
                              void* d_out, int out_size)
{
    const float* x      = (const float*)d_in[0];
    const float* w_attn = (const float*)d_in[1];
    const float* b_attn = (const float*)d_in[2];
    const float* w_proj = (const float*)d_in[3];
    const float* b_proj = (const float*)d_in[4];
    float* out = (float*)d_out;

    float *wat, *wpt, *yy;
    cudaGetSymbolAddress((void**)&wat, g_wat);
    cudaGetSymbolAddress((void**)&wpt, g_wpt);
    cudaGetSymbolAddress((void**)&yy,  g_y);

    cudaFuncSetAttribute(gemm_kernel,
                         cudaFuncAttributeMaxDynamicSharedMemorySize, GEMM_SMEM);
    cudaFuncSetAttribute(attn_kernel,
                         cudaFuncAttributeMaxDynamicSharedMemorySize, ATT_SMEM);

    transpose_round_kernel<<<dim3(N3_ / 32, C_ / 32), dim3(32, 8)>>>(w_attn, wat, C_, N3_);
    transpose_round_kernel<<<dim3(C_ / 32, C_ / 32), dim3(32, 8)>>>(w_proj, wpt, C_, C_);

    gemm_kernel<<<dim3(N3_ / 128, M_ / 128), 256, GEMM_SMEM>>>(x, wat, b_attn, nullptr, 0);
    attn_kernel<<<dim3(T_ / 128, BH_), 256, ATT_SMEM>>>();
    gemm_kernel<<<dim3(C_ / 128, M_ / 128), 256, GEMM_SMEM>>>(yy, wpt, b_proj, out, 1);
}

// round 4
// speedup vs baseline: 2.8147x; 1.0520x over previous
#include <cuda_runtime.h>

#define B_   4
#define T_   2048
#define C_   768
#define H_   12
#define D_   64
#define BH_  48
#define M_   8192
#define N3_  2304

// ---- scratch (device globals) ----
// All MMA k-dims stored gmem-permuted: within each 8-group, slot(k) = (k&3)*2 + (k>>2)
__device__ float g_xr[M_ * C_];      // x: rounded + k-permuted
__device__ float g_wat[N3_ * C_];    // w_attn^T, k-permuted
__device__ float g_wpt[C_ * C_];     // w_proj^T, k-permuted
__device__ float g_q[BH_ * T_ * D_]; // [bh][t][d-perm] *0.125 tf32
__device__ float g_k[BH_ * T_ * D_]; // [bh][t][d-perm] tf32
__device__ float g_vt[BH_ * D_ * T_];// [bh][d][t-perm] tf32
__device__ float g_y[M_ * C_];       // [m][c-perm] tf32

__device__ __forceinline__ float rna(float x) {
    unsigned r; asm("cvt.rna.tf32.f32 %0, %1;" : "=r"(r) : "f"(x));
    return __uint_as_float(r);
}
__device__ __forceinline__ unsigned fau(float x) { return __float_as_uint(x); }

__device__ __forceinline__ void mma8(float* c,
    unsigned a0, unsigned a1, unsigned a2, unsigned a3,
    unsigned b0, unsigned b1)
{
    asm volatile(
      "mma.sync.aligned.m16n8k8.row.col.f32.tf32.tf32.f32 "
      "{%0,%1,%2,%3},{%4,%5,%6,%7},{%8,%9},{%0,%1,%2,%3};"
      : "+f"(c[0]), "+f"(c[1]), "+f"(c[2]), "+f"(c[3])
      : "r"(a0), "r"(a1), "r"(a2), "r"(a3), "r"(b0), "r"(b1));
}

__device__ __forceinline__ void cp16(float* dst_smem, const float* src) {
    unsigned d = (unsigned)__cvta_generic_to_shared(dst_smem);
    asm volatile("cp.async.ca.shared.global [%0], [%1], 16;" :: "r"(d), "l"(src));
}
#define CP_COMMIT asm volatile("cp.async.commit_group;" ::: "memory")
#define CP_WAIT0  asm volatile("cp.async.wait_group 0;" ::: "memory")

// ---------------------------------------------------------------------------
// Prep: round x to tf32 + permute k within 8-groups.
// slot order per 8: holds k = 0,4,1,5,2,6,3,7
// ---------------------------------------------------------------------------
__global__ void roundperm_kernel(const float* __restrict__ in, float* __restrict__ out, int n8)
{
    for (int i = blockIdx.x * blockDim.x + threadIdx.x; i < n8; i += gridDim.x * blockDim.x) {
        float4 a = ((const float4*)in)[2 * i];
        float4 b = ((const float4*)in)[2 * i + 1];
        ((float4*)out)[2 * i]     = make_float4(rna(a.x), rna(b.x), rna(a.y), rna(b.y));
        ((float4*)out)[2 * i + 1] = make_float4(rna(a.z), rna(b.z), rna(a.w), rna(b.w));
    }
}

// Prep: transpose + round + k-permute. in [R][Cc] -> out [Cc][R(perm)]
__global__ void transpose_round_kernel(const float* __restrict__ in, float* __restrict__ out,
                                       int R, int Cc)
{
    __shared__ float tile[32][33];
    int bx = blockIdx.x * 32, by = blockIdx.y * 32;
    int x = bx + threadIdx.x;
    #pragma unroll
    for (int j = threadIdx.y; j < 32; j += 8)
        tile[j][threadIdx.x] = in[(by + j) * Cc + x];
    __syncthreads();
    int ox = by + threadIdx.x;
    int oxp = (ox & ~7) | (((ox & 3) << 1) | ((ox & 7) >> 2));
    #pragma unroll
    for (int j = threadIdx.y; j < 32; j += 8)
        out[(bx + j) * R + oxp] = rna(tile[threadIdx.x][j]);
}

// ---------------------------------------------------------------------------
// tf32 GEMM, 128x128 block, 8 warps (4m x 2n), warp tile 32x64, k-step 32.
// cp.async double-buffered staging of pre-permuted operands.
// ---------------------------------------------------------------------------
#define GP 40
#define GA (128 * GP)
#define GEMM_SMEM (4 * GA * 4)

__global__ __launch_bounds__(256, 2) void gemm_kernel(
    const float* __restrict__ A, const float* __restrict__ Bt,
    const float* __restrict__ bias, float* __restrict__ out, int mode)
{
    extern __shared__ float sm[];
    float* sAb = sm;
    float* sBb = sm + 2 * GA;

    const int m0 = blockIdx.y * 128;
    const int n0 = blockIdx.x * 128;
    const int tid = threadIdx.x;
    const int warp = tid >> 5, lane = tid & 31;
    const int g = lane >> 2, tig = lane & 3;
    const int wm = warp & 3, wn = warp >> 2;

    const int srow = tid >> 1;
    const int scol = (tid & 1) * 16;

    const float* Ap = A  + (long)(m0 + srow) * C_ + scol;
    const float* Bp = Bt + (long)(n0 + srow) * C_ + scol;

    float acc[2][8][4] = {};

#define GISSUE(buf, ks) do { \
    const float* ga_ = Ap + (ks) * 32; \
    const float* gb_ = Bp + (ks) * 32; \
    float* dA_ = sAb + (buf) * GA + srow * GP + scol; \
    float* dB_ = sBb + (buf) * GA + srow * GP + scol; \
    _Pragma("unroll") \
    for (int j_ = 0; j_ < 4; ++j_) { cp16(dA_ + j_ * 4, ga_ + j_ * 4); \
                                     cp16(dB_ + j_ * 4, gb_ + j_ * 4); } \
} while (0)

    GISSUE(0, 0); CP_COMMIT;

    const int NS = C_ / 32;  // 24
    for (int ks = 0; ks < NS; ++ks) {
        CP_WAIT0;
        __syncthreads();
        if (ks + 1 < NS) { GISSUE((ks + 1) & 1, ks + 1); CP_COMMIT; }

        const float* cA = sAb + (ks & 1) * GA;
        const float* cB = sBb + (ks & 1) * GA;
        #pragma unroll
        for (int kf = 0; kf < 4; ++kf) {
            unsigned a[2][4];
            #pragma unroll
            for (int mf = 0; mf < 2; ++mf) {
                const float* p = cA + (wm * 32 + mf * 16) * GP + kf * 8 + 2 * tig;
                float2 x0 = *(const float2*)(p + g * GP);
                float2 x1 = *(const float2*)(p + (g + 8) * GP);
                a[mf][0] = fau(x0.x); a[mf][1] = fau(x1.x);
                a[mf][2] = fau(x0.y); a[mf][3] = fau(x1.y);
            }
            #pragma unroll
            for (int nt = 0; nt < 8; ++nt) {
                float2 bv = *(const float2*)(cB + (wn * 64 + nt * 8 + g) * GP + kf * 8 + 2 * tig);
                unsigned b0 = fau(bv.x), b1 = fau(bv.y);
                mma8(acc[0][nt], a[0][0], a[0][1], a[0][2], a[0][3], b0, b1);
                mma8(acc[1][nt], a[1][0], a[1][1], a[1][2], a[1][3], b0, b1);
            }
        }
        __syncthreads();
    }

    const int c0 = 2 * tig, c1 = 2 * tig + 1;
    const int s0 = ((c0 & 3) << 1) | (c0 >> 2);
    const int s1 = ((c1 & 3) << 1) | (c1 >> 2);

    if (mode == 1) {
        #pragma unroll
        for (int mf = 0; mf < 2; ++mf) {
            int r = m0 + wm * 32 + mf * 16 + g;
            #pragma unroll
            for (int nt = 0; nt < 8; ++nt) {
                int c = n0 + wn * 64 + nt * 8 + c0;
                float b0 = bias[c], b1 = bias[c + 1];
                *(float2*)(out + (long)r * C_ + c) =
                    make_float2(acc[mf][nt][0] + b0, acc[mf][nt][1] + b1);
                *(float2*)(out + (long)(r + 8) * C_ + c) =
                    make_float2(acc[mf][nt][2] + b0, acc[mf][nt][3] + b1);
            }
        }
        return;
    }

    // QKV scatter epilogue (permuted destinations)
    const int ncw   = n0 + wn * 64;
    const int which = ncw / C_;
    const int hh    = (ncw % C_) >> 6;
    const int bb    = m0 >> 11;
    const int t0    = m0 & (T_ - 1);
    const int bh    = bb * H_ + hh;
    const int sg    = ((g & 3) << 1) | (g >> 2);   // t-slot for g_vt

    #pragma unroll
    for (int mf = 0; mf < 2; ++mf) {
        int t = t0 + wm * 32 + mf * 16 + g;
        int tp = (t - g) + sg;     // t with low-3 bits permuted
        #pragma unroll
        for (int nt = 0; nt < 8; ++nt) {
            int d8 = nt * 8;
            float b0 = bias[ncw + d8 + c0], b1 = bias[ncw + d8 + c1];
            float v0 = acc[mf][nt][0] + b0, v1 = acc[mf][nt][1] + b1;
            float v2 = acc[mf][nt][2] + b0, v3 = acc[mf][nt][3] + b1;
            if (which == 0) {
                float* p0 = g_q + ((long)bh * T_ + t) * D_ + d8;
                p0[s0] = rna(v0 * 0.125f); p0[s1] = rna(v1 * 0.125f);
                float* p1 = p0 + 8 * D_;
                p1[s0] = rna(v2 * 0.125f); p1[s1] = rna(v3 * 0.125f);
            } else if (which == 1) {
                float* p0 = g_k + ((long)bh * T_ + t) * D_ + d8;
                p0[s0] = rna(v0); p0[s1] = rna(v1);
                float* p1 = p0 + 8 * D_;
                p1[s0] = rna(v2); p1[s1] = rna(v3);
            } else {
                g_vt[((long)bh * D_ + d8 + c0) * T_ + tp]     = rna(v0);
                g_vt[((long)bh * D_ + d8 + c1) * T_ + tp]     = rna(v1);
                g_vt[((long)bh * D_ + d8 + c0) * T_ + tp + 8] = rna(v2);
                g_vt[((long)bh * D_ + d8 + c1) * T_ + tp + 8] = rna(v3);
            }
        }
    }
}

// ---------------------------------------------------------------------------
// Flash attention: 8 warps x 16 q-rows = 128 queries/block, K-tile 64,
// cp.async double-buffered K/V, heavy-first block order.
// ---------------------------------------------------------------------------
#define AP 72
#define KBUF (64 * AP)
#define ATT_SMEM ((4 * KBUF + 128 * AP) * 4)   // 110592 B

__global__ __launch_bounds__(256, 2) void attn_kernel()
{
    extern __shared__ float sm[];
    float* sK = sm;                 // 2 buffers
    float* sV = sm + 2 * KBUF;      // 2 buffers
    float* sP = sm + 4 * KBUF;

    const int qb = gridDim.x - 1 - blockIdx.x;   // heavy blocks first
    const int bh = blockIdx.y;
    const int bb = bh / H_, hh = bh % H_;
    const int q0 = qb * 128;
    const int tid = threadIdx.x;
    const int warp = tid >> 5, lane = tid & 31;
    const int g = lane >> 2, tig = lane & 3;

    const int srow = tid >> 2;         // 0..63
    const int scol = (tid & 3) * 16;

    const float* Kg = g_k  + ((long)bh * T_ + srow) * D_ + scol;
    const float* Vg = g_vt + ((long)bh * D_ + srow) * T_ + scol;

#define AISSUE(buf, kt) do { \
    const float* ks_ = Kg + (kt) * 64 * D_; \
    const float* vs_ = Vg + (kt) * 64; \
    float* kd_ = sK + (buf) * KBUF + srow * AP + scol; \
    float* vd_ = sV + (buf) * KBUF + srow * AP + scol; \
    _Pragma("unroll") \
    for (int j_ = 0; j_ < 4; ++j_) { cp16(kd_ + j_ * 4, ks_ + j_ * 4); \
                                     cp16(vd_ + j_ * 4, vs_ + j_ * 4); } \
} while (0)

    AISSUE(0, 0); CP_COMMIT;

    // Q fragments in registers (gmem already scaled, rounded, d-permuted)
    unsigned qf[8][4];
    {
        const float* r0 = g_q + ((long)bh * T_ + q0 + warp * 16 + g) * D_;
        const float* r1 = r0 + 8 * D_;
        #pragma unroll
        for (int kf = 0; kf < 8; ++kf) {
            float2 q0v = *(const float2*)(r0 + kf * 8 + 2 * tig);
            float2 q1v = *(const float2*)(r1 + kf * 8 + 2 * tig);
            qf[kf][0] = fau(q0v.x); qf[kf][2] = fau(q0v.y);
            qf[kf][1] = fau(q1v.x); qf[kf][3] = fau(q1v.y);
        }
    }

    float oacc[8][4] = {};
    float m0s = -1e30f, m1s = -1e30f, l0s = 0.0f, l1s = 0.0f;

    const int c0 = 2 * tig, c1 = 2 * tig + 1;
    const int s0 = ((c0 & 3) << 1) | (c0 >> 2);
    const int s1 = ((c1 & 3) << 1) | (c1 >> 2);
    const int prow = warp * 16 + g;

    const int ktmax = 2 * qb + 1;
    for (int kt = 0; kt <= ktmax; ++kt) {
        CP_WAIT0;
        __syncthreads();
        if (kt < ktmax) { AISSUE((kt + 1) & 1, kt + 1); CP_COMMIT; }

        const float* cK = sK + (kt & 1) * KBUF;
        const float* cV = sV + (kt & 1) * KBUF;

        // S = Q @ K^T (warp: 16 x 64)
        float sacc[8][4] = {};
        #pragma unroll
        for (int kf = 0; kf < 8; ++kf) {
            #pragma unroll
            for (int nt = 0; nt < 8; ++nt) {
                float2 bv = *(const float2*)(cK + (nt * 8 + g) * AP + kf * 8 + 2 * tig);
                mma8(sacc[nt], qf[kf][0], qf[kf][1], qf[kf][2], qf[kf][3],
                     fau(bv.x), fau(bv.y));
            }
        }

        const int rbase = q0 + warp * 16 + g;
        if (kt >= 2 * qb) {
            #pragma unroll
            for (int nt = 0; nt < 8; ++nt) {
                int cb = kt * 64 + nt * 8 + c0;
                if (cb     > rbase)     sacc[nt][0] = -1e30f;
                if (cb + 1 > rbase)     sacc[nt][1] = -1e30f;
                if (cb     > rbase + 8) sacc[nt][2] = -1e30f;
                if (cb + 1 > rbase + 8) sacc[nt][3] = -1e30f;
            }
        }

        float mx0 = -1e30f, mx1 = -1e30f;
        #pragma unroll
        for (int nt = 0; nt < 8; ++nt) {
            mx0 = fmaxf(mx0, fmaxf(sacc[nt][0], sacc[nt][1]));
            mx1 = fmaxf(mx1, fmaxf(sacc[nt][2], sacc[nt][3]));
        }
        mx0 = fmaxf(mx0, __shfl_xor_sync(0xffffffffu, mx0, 1));
        mx0 = fmaxf(mx0, __shfl_xor_sync(0xffffffffu, mx0, 2));
        mx1 = fmaxf(mx1, __shfl_xor_sync(0xffffffffu, mx1, 1));
        mx1 = fmaxf(mx1, __shfl_xor_sync(0xffffffffu, mx1, 2));

        float mn0 = fmaxf(m0s, mx0), mn1 = fmaxf(m1s, mx1);
        float al0 = __expf(m0s - mn0), al1 = __expf(m1s - mn1);
        m0s = mn0; m1s = mn1;

        float sum0 = 0.0f, sum1 = 0.0f;
        #pragma unroll
        for (int nt = 0; nt < 8; ++nt) {
            float p0 = __expf(sacc[nt][0] - mn0);
            float p1 = __expf(sacc[nt][1] - mn0);
            float p2 = __expf(sacc[nt][2] - mn1);
            float p3 = __expf(sacc[nt][3] - mn1);
            sum0 += p0 + p1; sum1 += p2 + p3;
            float* pr0 = sP + prow * AP + nt * 8;
            float* pr1 = sP + (prow + 8) * AP + nt * 8;
            pr0[s0] = rna(p0); pr0[s1] = rna(p1);
            pr1[s0] = rna(p2); pr1[s1] = rna(p3);
        }
        sum0 += __shfl_xor_sync(0xffffffffu, sum0, 1);
        sum0 += __shfl_xor_sync(0xffffffffu, sum0, 2);
        sum1 += __shfl_xor_sync(0xffffffffu, sum1, 1);
        sum1 += __shfl_xor_sync(0xffffffffu, sum1, 2);
        l0s = l0s * al0 + sum0;
        l1s = l1s * al1 + sum1;
        #pragma unroll
        for (int nt = 0; nt < 8; ++nt) {
            oacc[nt][0] *= al0; oacc[nt][1] *= al0;
            oacc[nt][2] *= al1; oacc[nt][3] *= al1;
        }
        __syncwarp();

        // O += P @ V
        #pragma unroll
        for (int kf = 0; kf < 8; ++kf) {
            const float* p = sP + (warp * 16) * AP + kf * 8 + 2 * tig;
            float2 x0 = *(const float2*)(p + g * AP);
            float2 x1 = *(const float2*)(p + (g + 8) * AP);
            unsigned a0 = fau(x0.x), a1 = fau(x1.x), a2 = fau(x0.y), a3 = fau(x1.y);
            #pragma unroll
            for (int nt = 0; nt < 8; ++nt) {
                float2 bv = *(const float2*)(cV + (nt * 8 + g) * AP + kf * 8 + 2 * tig);
                mma8(oacc[nt], a0, a1, a2, a3, fau(bv.x), fau(bv.y));
            }
        }
        __syncthreads();
    }

    // epilogue -> g_y (tf32-rounded, c-permuted for proj GEMM)
    const int row = q0 + warp * 16 + g;
    const float inv0 = 1.0f / l0s, inv1 = 1.0f / l1s;
    #pragma unroll
    for (int nt = 0; nt < 8; ++nt) {
        int colb = hh * 64 + nt * 8;
        float* y0 = g_y + ((long)bb * T_ + row) * C_ + colb;
        float* y1 = g_y + ((long)bb * T_ + row + 8) * C_ + colb;
        y0[s0] = rna(oacc[nt][0] * inv0); y0[s1] = rna(oacc[nt][1] * inv0);
        y1[s0] = rna(oacc[nt][2] * inv1); y1[s1] = rna(oacc[nt][3] * inv1);
    }
}

// ---------------------------------------------------------------------------
extern "C" void kernel_launch(void* const* d_in, const int* in_sizes, int n_in,
                              void* d_out, int out_size)
{
    const float* x      = (const float*)d_in[0];
    const float* w_attn = (const float*)d_in[1];
    const float* b_attn = (const float*)d_in[2];
    const float* w_proj = (const float*)d_in[3];
    const float* b_proj = (const float*)d_in[4];
    float* out = (float*)d_out;

    float *xr, *wat, *wpt, *yy;
    cudaGetSymbolAddress((void**)&xr,  g_xr);
    cudaGetSymbolAddress((void**)&wat, g_wat);
    cudaGetSymbolAddress((void**)&wpt, g_wpt);
    cudaGetSymbolAddress((void**)&yy,  g_y);

    cudaFuncSetAttribute(gemm_kernel,
                         cudaFuncAttributeMaxDynamicSharedMemorySize, GEMM_SMEM);
    cudaFuncSetAttribute(attn_kernel,
                         cudaFuncAttributeMaxDynamicSharedMemorySize, ATT_SMEM);

    roundperm_kernel<<<512, 256>>>(x, xr, M_ * C_ / 8);
    transpose_round_kernel<<<dim3(N3_ / 32, C_ / 32), dim3(32, 8)>>>(w_attn, wat, C_, N3_);
    transpose_round_kernel<<<dim3(C_ / 32, C_ / 32), dim3(32, 8)>>>(w_proj, wpt, C_, C_);

    gemm_kernel<<<dim3(N3_ / 128, M_ / 128), 256, GEMM_SMEM>>>(xr, wat, b_attn, nullptr, 0);
    attn_kernel<<<dim3(T_ / 128, BH_), 256, ATT_SMEM>>>();
    gemm_kernel<<<dim3(C_ / 128, M_ / 128), 256, GEMM_SMEM>>>(yy, wpt, b_proj, out, 1);
}